// round 14
// baseline (speedup 1.0000x reference)
#include <cuda_runtime.h>
#include <cuda_fp16.h>
#include <math.h>
#include <stdint.h>

// Problem constants
#define Lnum 8
#define Bb   8
#define Nn   1024
#define Ww   768
#define Hh   12
#define Cc   64
#define ROWS (Bb*Nn)          // 8192 token rows

// ---------------- scratch (no cudaMalloc allowed) ----------------
__device__ __half g_qkv[ROWS * 3 * Ww];
__device__ __half g_y  [ROWS * Ww];
__device__ __half g_at [ROWS * Ww];
__device__ __half g_fc [ROWS * 4 * Ww];
__device__ __half g_wq [Lnum * Ww * 3 * Ww];
__device__ __half g_wo [Lnum * Ww * Ww];
__device__ __half g_wf [Lnum * Ww * 4 * Ww];
__device__ __half g_wp [Lnum * 4 * Ww * Ww];

// =================== portable PTX helpers ===================
__device__ __forceinline__ uint32_t smem_to_u32(const void* smem_ptr) {
    uint32_t addr;
    asm("{ .reg .u64 tmp; cvta.to.shared.u64 tmp, %1; cvt.u32.u64 %0, tmp; }"
        : "=r"(addr) : "l"(smem_ptr));
    return addr;
}
__device__ __forceinline__ void ldsm_x4(uint32_t* r, uint32_t addr) {
    asm volatile("ldmatrix.sync.aligned.m8n8.x4.shared.b16 {%0,%1,%2,%3}, [%4];"
        : "=r"(r[0]), "=r"(r[1]), "=r"(r[2]), "=r"(r[3]) : "r"(addr));
}
__device__ __forceinline__ void ldsm_x2_t(uint32_t* r, uint32_t addr) {
    asm volatile("ldmatrix.sync.aligned.m8n8.x2.trans.shared.b16 {%0,%1}, [%2];"
        : "=r"(r[0]), "=r"(r[1]) : "r"(addr));
}
__device__ __forceinline__ void mma16816h(float* d, const uint32_t* a, const uint32_t* b) {
    asm volatile(
        "mma.sync.aligned.m16n8k16.row.col.f32.f16.f16.f32 "
        "{%0,%1,%2,%3}, {%4,%5,%6,%7}, {%8,%9}, {%0,%1,%2,%3};\n"
        : "+f"(d[0]), "+f"(d[1]), "+f"(d[2]), "+f"(d[3])
        : "r"(a[0]), "r"(a[1]), "r"(a[2]), "r"(a[3]), "r"(b[0]), "r"(b[1]));
}
__device__ __forceinline__ void cp16(uint32_t s, const void* g) {
    asm volatile("cp.async.ca.shared.global [%0], [%1], 16;" :: "r"(s), "l"(g));
}
#define CP_COMMIT() asm volatile("cp.async.commit_group;")
#define CP_WAIT1()  asm volatile("cp.async.wait_group 1;")
#define CP_WAIT0()  asm volatile("cp.async.wait_group 0;")

__device__ __forceinline__ uint32_t hpack(__half a, __half b) {
    uint16_t ua = *(uint16_t*)&a, ub = *(uint16_t*)&b;
    return (uint32_t)ua | ((uint32_t)ub << 16);
}
__device__ __forceinline__ uint32_t f16x2_of(float lo, float hi) {
    uint32_t d;
    asm("cvt.rn.f16x2.f32 %0, %1, %2;" : "=r"(d) : "f"(hi), "f"(lo));
    return d;
}
__device__ __forceinline__ uint32_t h2exp2(uint32_t x) {
    uint32_t d;
    asm("ex2.approx.f16x2 %0, %1;" : "=r"(d) : "r"(x));
    return d;
}
__device__ __forceinline__ float ex2f(float x) {
    float d;
    asm("ex2.approx.f32 %0, %1;" : "=f"(d) : "f"(x));
    return d;
}

// ---------------- weight conversion: fp32 -> f16 ----------------
__global__ void __launch_bounds__(256) cvt16_kernel(const float4* __restrict__ src,
                                                    uint2* __restrict__ dst,
                                                    int n4)
{
    int i = blockIdx.x * 256 + threadIdx.x;
    if (i >= n4) return;
    const float4 x = src[i];
    dst[i] = make_uint2(hpack(__float2half(x.x), __float2half(x.y)),
                        hpack(__float2half(x.z), __float2half(x.w)));
}

// ---------------- LayerNorm: warp per row, f16 out ----------------
__global__ void __launch_bounds__(256) ln_kernel(const float* __restrict__ x,
                                                 const float* __restrict__ g,
                                                 const float* __restrict__ b,
                                                 __half* __restrict__ y)
{
    const int warp = threadIdx.x >> 5;
    const int lane = threadIdx.x & 31;
    const int r = blockIdx.x * 8 + warp;
    const float* xr = x + (size_t)r * Ww;

    float4 v[6];
    float s = 0.f;
    #pragma unroll
    for (int i = 0; i < 6; i++) {
        v[i] = *(const float4*)(xr + (i * 32 + lane) * 4);
        s += v[i].x + v[i].y + v[i].z + v[i].w;
    }
    #pragma unroll
    for (int o = 16; o > 0; o >>= 1) s += __shfl_xor_sync(0xffffffffu, s, o);
    const float mean = s * (1.f / Ww);

    float s2 = 0.f;
    #pragma unroll
    for (int i = 0; i < 6; i++) {
        const float d0 = v[i].x - mean, d1 = v[i].y - mean;
        const float d2 = v[i].z - mean, d3 = v[i].w - mean;
        s2 += d0 * d0 + d1 * d1 + d2 * d2 + d3 * d3;
    }
    #pragma unroll
    for (int o = 16; o > 0; o >>= 1) s2 += __shfl_xor_sync(0xffffffffu, s2, o);
    const float w = rsqrtf(s2 * (1.f / Ww) + 1e-5f);

    #pragma unroll
    for (int i = 0; i < 6; i++) {
        const int c = (i * 32 + lane) * 4;
        const float4 gv = *(const float4*)(g + c);
        const float4 bv = *(const float4*)(b + c);
        const float o0 = (v[i].x - mean) * w * gv.x + bv.x;
        const float o1 = (v[i].y - mean) * w * gv.y + bv.y;
        const float o2 = (v[i].z - mean) * w * gv.z + bv.z;
        const float o3 = (v[i].w - mean) * w * gv.w + bv.w;
        *(uint2*)(y + (size_t)r * Ww + c) =
            make_uint2(hpack(__float2half(o0), __float2half(o1)),
                       hpack(__float2half(o2), __float2half(o3)));
    }
}

// =================== fp16 tensor-core GEMM, BK=32, 2-stage cp.async ===========
// MT: M-tile (128 or 64). Block = MT x 128, 8 warps (2m x 4n), warp MT/2 x 32.
// OUT: 0 = fp32 C (+res), 2 = f16 single.
// QSCALE: scale q columns (n%192<64) by 0.125*log2(e).
#define A_STRB 80
#define B_STRB 272
#define B_BYTES (32 * B_STRB)      // 8704

template<int RES, int GELU, int OUT, int QSCALE, int MT>
__global__ void __launch_bounds__(256, 2) gemm_tc(const __half* __restrict__ A,
                                                  const __half* __restrict__ B,
                                                  const float* __restrict__ bias,
                                                  const float* __restrict__ Rz,
                                                  float* __restrict__ C,
                                                  __half* __restrict__ Ch,
                                                  int M, int K, int N)
{
    constexpr int A_BYTES = MT * A_STRB;
    constexpr int OFF_B = A_BYTES;
    constexpr int BUFB = A_BYTES + B_BYTES;
    constexpr int MI = MT / 32;

    extern __shared__ char sm[];
    const uint32_t smem_base = smem_to_u32(sm);
    const int tid  = threadIdx.x;
    const int wid  = tid >> 5;
    const int lane = tid & 31;
    const int wm   = wid >> 2;
    const int wn   = wid & 3;
    const int n0 = blockIdx.x * 128;
    const int m0 = blockIdx.y * MT;

    float acc[MI][4][4];
    #pragma unroll
    for (int i = 0; i < MI; i++)
        #pragma unroll
        for (int j = 0; j < 4; j++)
            #pragma unroll
            for (int q = 0; q < 4; q++) acc[i][j][q] = 0.f;

    const int NC = K / 32;

    const int a_r = (MT == 128) ? (tid >> 1) : (tid >> 2);
    const int a_p = (MT == 128) ? ((tid & 1) * 2) : (tid & 3);
    const int b_r = tid >> 3;
    const int b_p = (tid & 7) * 2;

    auto issue_chunk = [&](int kc, int bsel) {
        const uint32_t buf = smem_base + bsel * BUFB;
        const uint32_t aoff = (uint32_t)a_r * A_STRB + a_p * 16;
        const __half* ap = A + (size_t)(m0 + a_r) * K + kc * 32 + a_p * 8;
        cp16(buf + aoff, ap);
        if (MT == 128) cp16(buf + aoff + 16, ap + 8);
        const uint32_t boff = (uint32_t)b_r * B_STRB + b_p * 16;
        const __half* bp = B + (size_t)(kc * 32 + b_r) * N + n0 + b_p * 8;
        cp16(buf + OFF_B + boff,      bp);
        cp16(buf + OFF_B + boff + 16, bp + 8);
    };

    const uint32_t a_lrow = (uint32_t)(wm * (MT / 2) + (lane & 15));
    const uint32_t a_koff = (uint32_t)(8 * (lane >> 4));
    const uint32_t b_lrow = (uint32_t)(lane & 15);
    const uint32_t b_noff = (uint32_t)(wn * 32);

    issue_chunk(0, 0); CP_COMMIT();
    issue_chunk(1, 1); CP_COMMIT();

    for (int ic = 0; ic < NC; ic++) {
        CP_WAIT1();
        __syncthreads();

        const uint32_t buf = smem_base + (ic & 1) * BUFB;
        #pragma unroll
        for (int k16 = 0; k16 < 2; k16++) {
            uint32_t ah[MI][4];
            #pragma unroll
            for (int mi = 0; mi < MI; mi++) {
                const uint32_t aoff = (a_lrow + mi * 16) * A_STRB
                                    + (k16 * 16 + a_koff) * 2;
                ldsm_x4(ah[mi], buf + aoff);
            }
            #pragma unroll
            for (int ni = 0; ni < 4; ni++) {
                uint32_t bh[2];
                const uint32_t boff = (k16 * 16 + b_lrow) * B_STRB
                                    + (b_noff + ni * 8) * 2;
                ldsm_x2_t(bh, buf + OFF_B + boff);
                #pragma unroll
                for (int mi = 0; mi < MI; mi++)
                    mma16816h(acc[mi][ni], ah[mi], bh);
            }
        }

        __syncthreads();
        if (ic + 2 < NC) issue_chunk(ic + 2, ic & 1);
        CP_COMMIT();
    }

    const int g = lane >> 2;
    const int t = lane & 3;
    #pragma unroll
    for (int mi = 0; mi < MI; mi++) {
        #pragma unroll
        for (int half = 0; half < 2; half++) {
            const int m_ = m0 + wm * (MT / 2) + mi * 16 + g + half * 8;
            #pragma unroll
            for (int ni = 0; ni < 4; ni++) {
                const int n_ = n0 + wn * 32 + ni * 8 + 2 * t;
                float v0 = acc[mi][ni][half * 2 + 0] + bias[n_];
                float v1 = acc[mi][ni][half * 2 + 1] + bias[n_ + 1];
                if (GELU) {
                    v0 = 0.5f * v0 * (1.0f + erff(v0 * 0.70710678118654752f));
                    v1 = 0.5f * v1 * (1.0f + erff(v1 * 0.70710678118654752f));
                }
                if (RES) {
                    const float2 rv = *(const float2*)(Rz + (size_t)m_ * N + n_);
                    v0 += rv.x; v1 += rv.y;
                }
                if (QSCALE) {
                    if ((n_ % 192) < 64) { v0 *= 0.18033688011112042f; v1 *= 0.18033688011112042f; }
                }
                if (OUT == 2) {
                    *(uint32_t*)(Ch + (size_t)m_ * N + n_) =
                        hpack(__float2half(v0), __float2half(v1));
                } else {
                    *(float2*)(C + (size_t)m_ * N + n_) = make_float2(v0, v1);
                }
            }
        }
    }
}

#define GEMM_SMEM128 (2 * (128 * A_STRB + B_BYTES))   // 37888
#define GEMM_SMEM64  (2 * (64 * A_STRB + B_BYTES))    // 27648

// =================== fp16 flash attention, f16x2 exp2 softmax, ones-MMA row sums =========
#define AT_STR 144
#define AT_OFF_KV (128*AT_STR)
#define AT_BUF    (2*64*AT_STR)
#define AT_K 0
#define AT_V (64*AT_STR)
#define ATTN_SMEM (AT_OFF_KV + 2*AT_BUF)

__global__ void __launch_bounds__(256, 2) attn_tc(const __half* __restrict__ qkv,
                                                  __half* __restrict__ out)
{
    extern __shared__ char sm[];
    const uint32_t sb = smem_to_u32(sm);
    const int tid  = threadIdx.x;
    const int warp = tid >> 5;
    const int lane = tid & 31;
    const int g    = lane >> 2;
    const int t    = lane & 3;
    const int blk  = blockIdx.x;
    const int bh   = blk >> 3;
    const int rb   = blk & 7;
    const int b    = bh / Hh;
    const int h    = bh % Hh;
    const int rowbase = b * Nn + rb * 128;
    const int colq = h * 3 * Cc;

    #pragma unroll
    for (int i = 0; i < 4; i++) {
        const int flat = tid + i * 256;
        const int row = flat >> 3, c8 = flat & 7;
        const size_t goff = (size_t)(rowbase + row) * (3 * Ww) + colq + c8 * 8;
        cp16(sb + row * AT_STR + c8 * 16, qkv + goff);
    }
    auto issue_kv = [&](int kt, int bsel) {
        const uint32_t kvb = sb + AT_OFF_KV + bsel * AT_BUF;
        #pragma unroll
        for (int i = 0; i < 2; i++) {
            const int flat = tid + i * 256;
            const int row = flat >> 3, c8 = flat & 7;
            const size_t go = (size_t)(b * Nn + kt * 64 + row) * (3 * Ww) + colq + c8 * 8;
            const uint32_t so = row * AT_STR + c8 * 16;
            cp16(kvb + AT_K + so, qkv + go + 64);
            cp16(kvb + AT_V + so, qkv + go + 128);
        }
    };
    issue_kv(0, 0);
    CP_COMMIT();

    float m0r = -1e30f, m1r = -1e30f, l0r = 0.f, l1r = 0.f;
    float O[8][4];
    #pragma unroll
    for (int j = 0; j < 8; j++)
        #pragma unroll
        for (int q = 0; q < 4; q++) O[j][q] = 0.f;

    const uint32_t q_lrow = (uint32_t)(16 * warp + (lane & 15));
    const uint32_t q_koff = (uint32_t)(8 * (lane >> 4));
    const int k_nrow = (lane & 7) + ((lane >> 4) << 3);
    const int k_koff = ((lane >> 3) & 1) * 8;
    const int v_krow = lane & 15;
    const uint32_t ones2[2] = {0x3C003C00u, 0x3C003C00u};

    for (int kt = 0; kt < 16; kt++) {
        if (kt + 1 < 16) { issue_kv(kt + 1, (kt + 1) & 1); CP_COMMIT(); CP_WAIT1(); }
        else CP_WAIT0();
        __syncthreads();

        const uint32_t kvb = sb + AT_OFF_KV + (kt & 1) * AT_BUF;

        float s[8][4];
        #pragma unroll
        for (int j = 0; j < 8; j++)
            #pragma unroll
            for (int q = 0; q < 4; q++) s[j][q] = 0.f;

        #pragma unroll
        for (int k16 = 0; k16 < 4; k16++) {
            uint32_t ah[4];
            const uint32_t qo = q_lrow * AT_STR + (k16 * 16 + q_koff) * 2;
            ldsm_x4(ah, sb + qo);
            #pragma unroll
            for (int jj = 0; jj < 4; jj++) {
                uint32_t kh[4];
                const uint32_t ko = (uint32_t)(16 * jj + k_nrow) * AT_STR
                                  + (k16 * 16 + k_koff) * 2;
                ldsm_x4(kh, kvb + AT_K + ko);
                mma16816h(s[2*jj],   ah, &kh[0]);
                mma16816h(s[2*jj+1], ah, &kh[2]);
            }
        }

        float mx0 = -1e30f, mx1 = -1e30f;
        #pragma unroll
        for (int j = 0; j < 8; j++) {
            mx0 = fmaxf(mx0, fmaxf(s[j][0], s[j][1]));
            mx1 = fmaxf(mx1, fmaxf(s[j][2], s[j][3]));
        }
        mx0 = fmaxf(mx0, __shfl_xor_sync(0xffffffffu, mx0, 1));
        mx0 = fmaxf(mx0, __shfl_xor_sync(0xffffffffu, mx0, 2));
        mx1 = fmaxf(mx1, __shfl_xor_sync(0xffffffffu, mx1, 1));
        mx1 = fmaxf(mx1, __shfl_xor_sync(0xffffffffu, mx1, 2));
        const float mn0 = fmaxf(m0r, mx0);
        const float mn1 = fmaxf(m1r, mx1);
        const float al0 = ex2f(m0r - mn0);
        const float al1 = ex2f(m1r - mn1);
        m0r = mn0; m1r = mn1;

        uint32_t ph[8][2];
        #pragma unroll
        for (int j = 0; j < 8; j++) {
            ph[j][0] = h2exp2(f16x2_of(s[j][0] - mn0, s[j][1] - mn0));
            ph[j][1] = h2exp2(f16x2_of(s[j][2] - mn1, s[j][3] - mn1));
        }

        float lacc[4] = {0.f, 0.f, 0.f, 0.f};
        #pragma unroll
        for (int kk = 0; kk < 4; kk++) {
            uint32_t aph[4] = {ph[2*kk][0], ph[2*kk][1], ph[2*kk+1][0], ph[2*kk+1][1]};
            mma16816h(lacc, aph, ones2);
        }
        l0r = l0r * al0 + lacc[0];
        l1r = l1r * al1 + lacc[2];

        #pragma unroll
        for (int j = 0; j < 8; j++) {
            O[j][0] *= al0; O[j][1] *= al0; O[j][2] *= al1; O[j][3] *= al1;
        }

        #pragma unroll
        for (int kk = 0; kk < 4; kk++) {
            uint32_t aph[4] = {ph[2*kk][0], ph[2*kk][1], ph[2*kk+1][0], ph[2*kk+1][1]};
            #pragma unroll
            for (int j = 0; j < 8; j++) {
                uint32_t vh[2];
                const uint32_t vo = (uint32_t)(kk * 16 + v_krow) * AT_STR + (8 * j) * 2;
                ldsm_x2_t(vh, kvb + AT_V + vo);
                mma16816h(O[j], aph, vh);
            }
        }
        __syncthreads();
    }

    const float inv0 = 1.f / l0r;
    const float inv1 = 1.f / l1r;
    const int row0 = rowbase + 16 * warp + g;
    const int row1 = row0 + 8;
    #pragma unroll
    for (int j = 0; j < 8; j++) {
        const int col = h * Cc + 8 * j + 2 * t;
        *(uint32_t*)(out + (size_t)row0 * Ww + col) =
            hpack(__float2half(O[j][0] * inv0), __float2half(O[j][1] * inv0));
        *(uint32_t*)(out + (size_t)row1 * Ww + col) =
            hpack(__float2half(O[j][2] * inv1), __float2half(O[j][3] * inv1));
    }
}

// ---------------- launcher ----------------
extern "C" void kernel_launch(void* const* d_in, const int* in_sizes, int n_in,
                              void* d_out, int out_size)
{
    const float* x    = (const float*)d_in[0];
    const float* Wqkv = (const float*)d_in[1];
    const float* bqkv = (const float*)d_in[2];
    const float* Wo   = (const float*)d_in[3];
    const float* bo   = (const float*)d_in[4];
    const float* Wfc  = (const float*)d_in[5];
    const float* bfc  = (const float*)d_in[6];
    const float* Wpr  = (const float*)d_in[7];
    const float* bpr  = (const float*)d_in[8];
    const float* g1   = (const float*)d_in[9];
    const float* b1   = (const float*)d_in[10];
    const float* g2   = (const float*)d_in[11];
    const float* b2   = (const float*)d_in[12];

    float* h = (float*)d_out;

    __half *pqkv, *py, *pat, *pfc, *wq, *wo, *wf, *wp;
    cudaGetSymbolAddress((void**)&pqkv, g_qkv);
    cudaGetSymbolAddress((void**)&py,   g_y);
    cudaGetSymbolAddress((void**)&pat,  g_at);
    cudaGetSymbolAddress((void**)&pfc,  g_fc);
    cudaGetSymbolAddress((void**)&wq,   g_wq);
    cudaGetSymbolAddress((void**)&wo,   g_wo);
    cudaGetSymbolAddress((void**)&wf,   g_wf);
    cudaGetSymbolAddress((void**)&wp,   g_wp);

    cudaFuncSetAttribute(gemm_tc<0,0,2,1,128>, cudaFuncAttributeMaxDynamicSharedMemorySize, GEMM_SMEM128);
    cudaFuncSetAttribute(gemm_tc<0,1,2,0,128>, cudaFuncAttributeMaxDynamicSharedMemorySize, GEMM_SMEM128);
    cudaFuncSetAttribute(gemm_tc<1,0,0,0,64>,  cudaFuncAttributeMaxDynamicSharedMemorySize, GEMM_SMEM64);
    cudaFuncSetAttribute(attn_tc,              cudaFuncAttributeMaxDynamicSharedMemorySize, ATTN_SMEM);

    cudaMemcpyAsync(h, x, (size_t)ROWS * Ww * sizeof(float), cudaMemcpyDeviceToDevice);

    {
        int n4;
        n4 = Lnum * Ww * 3 * Ww / 4;
        cvt16_kernel<<<(n4 + 255) / 256, 256>>>((const float4*)Wqkv, (uint2*)wq, n4);
        n4 = Lnum * Ww * Ww / 4;
        cvt16_kernel<<<(n4 + 255) / 256, 256>>>((const float4*)Wo,   (uint2*)wo, n4);
        n4 = Lnum * Ww * 4 * Ww / 4;
        cvt16_kernel<<<(n4 + 255) / 256, 256>>>((const float4*)Wfc,  (uint2*)wf, n4);
        n4 = Lnum * 4 * Ww * Ww / 4;
        cvt16_kernel<<<(n4 + 255) / 256, 256>>>((const float4*)Wpr,  (uint2*)wp, n4);
    }

    for (int l = 0; l < Lnum; l++) {
        const size_t oq = (size_t)l * Ww * 3 * Ww;
        const size_t oo = (size_t)l * Ww * Ww;
        const size_t of = (size_t)l * Ww * 4 * Ww;
        const size_t op = (size_t)l * 4 * Ww * Ww;
        const float* bq  = bqkv + (size_t)l * 3 * Ww;
        const float* bo_ = bo   + (size_t)l * Ww;
        const float* bf  = bfc  + (size_t)l * 4 * Ww;
        const float* bp  = bpr  + (size_t)l * Ww;

        ln_kernel<<<ROWS / 8, 256>>>(h, g1 + l * Ww, b1 + l * Ww, py);
        // qkv: M128 tile (1152 blocks, ~97% wave eff)
        gemm_tc<0,0,2,1,128><<<dim3(3 * Ww / 128, ROWS / 128), 256, GEMM_SMEM128>>>(
            py, wq + oq, bq, nullptr, nullptr, pqkv, ROWS, Ww, 3 * Ww);
        attn_tc<<<Bb * Hh * (Nn / 128), 256, ATTN_SMEM>>>(pqkv, pat);
        // o-proj: M64 tile (768 blocks instead of 384 -> better tail)
        gemm_tc<1,0,0,0,64><<<dim3(Ww / 128, ROWS / 64), 256, GEMM_SMEM64>>>(
            pat, wo + oo, bo_, h, h, nullptr, ROWS, Ww, Ww);
        ln_kernel<<<ROWS / 8, 256>>>(h, g2 + l * Ww, b2 + l * Ww, py);
        // fc: M128
        gemm_tc<0,1,2,0,128><<<dim3(4 * Ww / 128, ROWS / 128), 256, GEMM_SMEM128>>>(
            py, wf + of, bf, nullptr, nullptr, pfc, ROWS, Ww, 4 * Ww);
        // pr-proj: M64 tile
        gemm_tc<1,0,0,0,64><<<dim3(Ww / 128, ROWS / 64), 256, GEMM_SMEM64>>>(
            pfc, wp + op, bp, h, h, nullptr, ROWS, 4 * Ww, Ww);
    }
}

// round 15
// speedup vs baseline: 1.0838x; 1.0838x over previous
#include <cuda_runtime.h>
#include <cuda_fp16.h>
#include <math.h>
#include <stdint.h>

// Problem constants
#define Lnum 8
#define Bb   8
#define Nn   1024
#define Ww   768
#define Hh   12
#define Cc   64
#define ROWS (Bb*Nn)          // 8192 token rows

// ---------------- scratch (no cudaMalloc allowed) ----------------
__device__ __half g_qkv[ROWS * 3 * Ww];
__device__ __half g_y  [ROWS * Ww];
__device__ __half g_at [ROWS * Ww];
__device__ __half g_fc [ROWS * 4 * Ww];
__device__ __half g_wq [Lnum * Ww * 3 * Ww];
__device__ __half g_wo [Lnum * Ww * Ww];
__device__ __half g_wf [Lnum * Ww * 4 * Ww];
__device__ __half g_wp [Lnum * 4 * Ww * Ww];

// =================== portable PTX helpers ===================
__device__ __forceinline__ uint32_t smem_to_u32(const void* smem_ptr) {
    uint32_t addr;
    asm("{ .reg .u64 tmp; cvta.to.shared.u64 tmp, %1; cvt.u32.u64 %0, tmp; }"
        : "=r"(addr) : "l"(smem_ptr));
    return addr;
}
__device__ __forceinline__ void ldsm_x4(uint32_t* r, uint32_t addr) {
    asm volatile("ldmatrix.sync.aligned.m8n8.x4.shared.b16 {%0,%1,%2,%3}, [%4];"
        : "=r"(r[0]), "=r"(r[1]), "=r"(r[2]), "=r"(r[3]) : "r"(addr));
}
__device__ __forceinline__ void ldsm_x2_t(uint32_t* r, uint32_t addr) {
    asm volatile("ldmatrix.sync.aligned.m8n8.x2.trans.shared.b16 {%0,%1}, [%2];"
        : "=r"(r[0]), "=r"(r[1]) : "r"(addr));
}
__device__ __forceinline__ void ldsm_x4_t(uint32_t* r, uint32_t addr) {
    asm volatile("ldmatrix.sync.aligned.m8n8.x4.trans.shared.b16 {%0,%1,%2,%3}, [%4];"
        : "=r"(r[0]), "=r"(r[1]), "=r"(r[2]), "=r"(r[3]) : "r"(addr));
}
__device__ __forceinline__ void mma16816h(float* d, const uint32_t* a, const uint32_t* b) {
    asm volatile(
        "mma.sync.aligned.m16n8k16.row.col.f32.f16.f16.f32 "
        "{%0,%1,%2,%3}, {%4,%5,%6,%7}, {%8,%9}, {%0,%1,%2,%3};\n"
        : "+f"(d[0]), "+f"(d[1]), "+f"(d[2]), "+f"(d[3])
        : "r"(a[0]), "r"(a[1]), "r"(a[2]), "r"(a[3]), "r"(b[0]), "r"(b[1]));
}
__device__ __forceinline__ void cp16(uint32_t s, const void* g) {
    asm volatile("cp.async.cg.shared.global [%0], [%1], 16;" :: "r"(s), "l"(g));
}
#define CP_COMMIT() asm volatile("cp.async.commit_group;")
#define CP_WAIT1()  asm volatile("cp.async.wait_group 1;")
#define CP_WAIT0()  asm volatile("cp.async.wait_group 0;")

__device__ __forceinline__ uint32_t hpack(__half a, __half b) {
    uint16_t ua = *(uint16_t*)&a, ub = *(uint16_t*)&b;
    return (uint32_t)ua | ((uint32_t)ub << 16);
}
__device__ __forceinline__ uint32_t f16x2_of(float lo, float hi) {
    uint32_t d;
    asm("cvt.rn.f16x2.f32 %0, %1, %2;" : "=r"(d) : "f"(hi), "f"(lo));
    return d;
}
__device__ __forceinline__ uint32_t h2exp2(uint32_t x) {
    uint32_t d;
    asm("ex2.approx.f16x2 %0, %1;" : "=r"(d) : "r"(x));
    return d;
}
__device__ __forceinline__ float ex2f(float x) {
    float d;
    asm("ex2.approx.f32 %0, %1;" : "=f"(d) : "f"(x));
    return d;
}

// ---------------- weight conversion: fp32 -> f16 ----------------
__global__ void __launch_bounds__(256) cvt16_kernel(const float4* __restrict__ src,
                                                    uint2* __restrict__ dst,
                                                    int n4)
{
    int i = blockIdx.x * 256 + threadIdx.x;
    if (i >= n4) return;
    const float4 x = src[i];
    dst[i] = make_uint2(hpack(__float2half(x.x), __float2half(x.y)),
                        hpack(__float2half(x.z), __float2half(x.w)));
}

// ---------------- LayerNorm: warp per row, f16 out ----------------
__global__ void __launch_bounds__(256) ln_kernel(const float* __restrict__ x,
                                                 const float* __restrict__ g,
                                                 const float* __restrict__ b,
                                                 __half* __restrict__ y)
{
    const int warp = threadIdx.x >> 5;
    const int lane = threadIdx.x & 31;
    const int r = blockIdx.x * 8 + warp;
    const float* xr = x + (size_t)r * Ww;

    float4 v[6];
    float s = 0.f;
    #pragma unroll
    for (int i = 0; i < 6; i++) {
        v[i] = *(const float4*)(xr + (i * 32 + lane) * 4);
        s += v[i].x + v[i].y + v[i].z + v[i].w;
    }
    #pragma unroll
    for (int o = 16; o > 0; o >>= 1) s += __shfl_xor_sync(0xffffffffu, s, o);
    const float mean = s * (1.f / Ww);

    float s2 = 0.f;
    #pragma unroll
    for (int i = 0; i < 6; i++) {
        const float d0 = v[i].x - mean, d1 = v[i].y - mean;
        const float d2 = v[i].z - mean, d3 = v[i].w - mean;
        s2 += d0 * d0 + d1 * d1 + d2 * d2 + d3 * d3;
    }
    #pragma unroll
    for (int o = 16; o > 0; o >>= 1) s2 += __shfl_xor_sync(0xffffffffu, s2, o);
    const float w = rsqrtf(s2 * (1.f / Ww) + 1e-5f);

    #pragma unroll
    for (int i = 0; i < 6; i++) {
        const int c = (i * 32 + lane) * 4;
        const float4 gv = *(const float4*)(g + c);
        const float4 bv = *(const float4*)(b + c);
        const float o0 = (v[i].x - mean) * w * gv.x + bv.x;
        const float o1 = (v[i].y - mean) * w * gv.y + bv.y;
        const float o2 = (v[i].z - mean) * w * gv.z + bv.z;
        const float o3 = (v[i].w - mean) * w * gv.w + bv.w;
        *(uint2*)(y + (size_t)r * Ww + c) =
            make_uint2(hpack(__float2half(o0), __float2half(o1)),
                       hpack(__float2half(o2), __float2half(o3)));
    }
}

// =================== fp16 tensor-core GEMM, BK=32, 2-stage cp.async, 2 CTAs/SM (R13) ======
// OUT: 0 = fp32 C (+res), 2 = f16 single.
// QSCALE: scale q columns (n%192<64) by 0.125*log2(e).
#define A_STRB 80
#define B_STRB 272
#define A_BYTES (128 * A_STRB)     // 10240
#define B_BYTES (32 * B_STRB)      // 8704
#define OFF_B   A_BYTES
#define BUF_BYTES (A_BYTES + B_BYTES)   // 18944
#define GEMM_SMEM (2 * BUF_BYTES)       // 37888

template<int RES, int GELU, int OUT, int QSCALE>
__global__ void __launch_bounds__(256, 2) gemm_tc(const __half* __restrict__ A,
                                                  const __half* __restrict__ B,
                                                  const float* __restrict__ bias,
                                                  const float* __restrict__ Rz,
                                                  float* __restrict__ C,
                                                  __half* __restrict__ Ch,
                                                  int M, int K, int N)
{
    extern __shared__ char sm[];
    const uint32_t smem_base = smem_to_u32(sm);
    const int tid  = threadIdx.x;
    const int wid  = tid >> 5;
    const int lane = tid & 31;
    const int wm   = wid >> 2;
    const int wn   = wid & 3;
    const int n0 = blockIdx.x * 128;
    const int m0 = blockIdx.y * 128;

    float acc[4][4][4];
    #pragma unroll
    for (int i = 0; i < 4; i++)
        #pragma unroll
        for (int j = 0; j < 4; j++)
            #pragma unroll
            for (int q = 0; q < 4; q++) acc[i][j][q] = 0.f;

    const int NC = K / 32;

    const int a_r = tid >> 1;
    const int a_p = (tid & 1) * 2;
    const int b_r = tid >> 3;
    const int b_p = (tid & 7) * 2;

    auto issue_chunk = [&](int kc, int bsel) {
        const uint32_t buf = smem_base + bsel * BUF_BYTES;
        const uint32_t aoff = (uint32_t)a_r * A_STRB + a_p * 16;
        const __half* ap = A + (size_t)(m0 + a_r) * K + kc * 32 + a_p * 8;
        cp16(buf + aoff,      ap);
        cp16(buf + aoff + 16, ap + 8);
        const uint32_t boff = (uint32_t)b_r * B_STRB + b_p * 16;
        const __half* bp = B + (size_t)(kc * 32 + b_r) * N + n0 + b_p * 8;
        cp16(buf + OFF_B + boff,      bp);
        cp16(buf + OFF_B + boff + 16, bp + 8);
    };

    const uint32_t a_lrow = (uint32_t)(wm * 64 + (lane & 15));
    const uint32_t a_koff = (uint32_t)(8 * (lane >> 4));
    const uint32_t b_lrow = (uint32_t)(lane & 15);
    const uint32_t b_noff = (uint32_t)(wn * 32);

    issue_chunk(0, 0); CP_COMMIT();
    issue_chunk(1, 1); CP_COMMIT();

    for (int ic = 0; ic < NC; ic++) {
        CP_WAIT1();
        __syncthreads();

        const uint32_t buf = smem_base + (ic & 1) * BUF_BYTES;
        #pragma unroll
        for (int k16 = 0; k16 < 2; k16++) {
            uint32_t ah[4][4];
            #pragma unroll
            for (int mi = 0; mi < 4; mi++) {
                const uint32_t aoff = (a_lrow + mi * 16) * A_STRB
                                    + (k16 * 16 + a_koff) * 2;
                ldsm_x4(ah[mi], buf + aoff);
            }
            #pragma unroll
            for (int ni = 0; ni < 4; ni++) {
                uint32_t bh[2];
                const uint32_t boff = (k16 * 16 + b_lrow) * B_STRB
                                    + (b_noff + ni * 8) * 2;
                ldsm_x2_t(bh, buf + OFF_B + boff);
                #pragma unroll
                for (int mi = 0; mi < 4; mi++)
                    mma16816h(acc[mi][ni], ah[mi], bh);
            }
        }

        __syncthreads();
        if (ic + 2 < NC) issue_chunk(ic + 2, ic & 1);
        CP_COMMIT();
    }

    const int g = lane >> 2;
    const int t = lane & 3;
    #pragma unroll
    for (int mi = 0; mi < 4; mi++) {
        #pragma unroll
        for (int half = 0; half < 2; half++) {
            const int m_ = m0 + wm * 64 + mi * 16 + g + half * 8;
            #pragma unroll
            for (int ni = 0; ni < 4; ni++) {
                const int n_ = n0 + wn * 32 + ni * 8 + 2 * t;
                float v0 = acc[mi][ni][half * 2 + 0] + bias[n_];
                float v1 = acc[mi][ni][half * 2 + 1] + bias[n_ + 1];
                if (GELU) {
                    v0 = 0.5f * v0 * (1.0f + erff(v0 * 0.70710678118654752f));
                    v1 = 0.5f * v1 * (1.0f + erff(v1 * 0.70710678118654752f));
                }
                if (RES) {
                    const float2 rv = *(const float2*)(Rz + (size_t)m_ * N + n_);
                    v0 += rv.x; v1 += rv.y;
                }
                if (QSCALE) {
                    if ((n_ % 192) < 64) { v0 *= 0.18033688011112042f; v1 *= 0.18033688011112042f; }
                }
                if (OUT == 2) {
                    *(uint32_t*)(Ch + (size_t)m_ * N + n_) =
                        hpack(__float2half(v0), __float2half(v1));
                } else {
                    *(float2*)(C + (size_t)m_ * N + n_) = make_float2(v0, v1);
                }
            }
        }
    }
}

// =================== fp16 flash attention, f16x2 exp2 softmax, ones-MMA row sums =========
// q prescaled by 0.125*log2(e); probabilities p = 2^(s - m).
#define AT_STR 144
#define AT_OFF_KV (128*AT_STR)
#define AT_BUF    (2*64*AT_STR)
#define AT_K 0
#define AT_V (64*AT_STR)
#define ATTN_SMEM (AT_OFF_KV + 2*AT_BUF)

__global__ void __launch_bounds__(256, 2) attn_tc(const __half* __restrict__ qkv,
                                                  __half* __restrict__ out)
{
    extern __shared__ char sm[];
    const uint32_t sb = smem_to_u32(sm);
    const int tid  = threadIdx.x;
    const int warp = tid >> 5;
    const int lane = tid & 31;
    const int g    = lane >> 2;
    const int t    = lane & 3;
    const int blk  = blockIdx.x;
    const int bh   = blk >> 3;
    const int rb   = blk & 7;
    const int b    = bh / Hh;
    const int h    = bh % Hh;
    const int rowbase = b * Nn + rb * 128;
    const int colq = h * 3 * Cc;

    #pragma unroll
    for (int i = 0; i < 4; i++) {
        const int flat = tid + i * 256;
        const int row = flat >> 3, c8 = flat & 7;
        const size_t goff = (size_t)(rowbase + row) * (3 * Ww) + colq + c8 * 8;
        cp16(sb + row * AT_STR + c8 * 16, qkv + goff);
    }
    auto issue_kv = [&](int kt, int bsel) {
        const uint32_t kvb = sb + AT_OFF_KV + bsel * AT_BUF;
        #pragma unroll
        for (int i = 0; i < 2; i++) {
            const int flat = tid + i * 256;
            const int row = flat >> 3, c8 = flat & 7;
            const size_t go = (size_t)(b * Nn + kt * 64 + row) * (3 * Ww) + colq + c8 * 8;
            const uint32_t so = row * AT_STR + c8 * 16;
            cp16(kvb + AT_K + so, qkv + go + 64);
            cp16(kvb + AT_V + so, qkv + go + 128);
        }
    };
    issue_kv(0, 0);
    CP_COMMIT();

    float m0r = -1e30f, m1r = -1e30f, l0r = 0.f, l1r = 0.f;
    float O[8][4];
    #pragma unroll
    for (int j = 0; j < 8; j++)
        #pragma unroll
        for (int q = 0; q < 4; q++) O[j][q] = 0.f;

    const uint32_t q_lrow = (uint32_t)(16 * warp + (lane & 15));
    const uint32_t q_koff = (uint32_t)(8 * (lane >> 4));
    const int k_nrow = (lane & 7) + ((lane >> 4) << 3);
    const int k_koff = ((lane >> 3) & 1) * 8;
    const int v_row_l  = (lane & 7) + ((lane >> 3) & 1) * 8;
    const int v_coladd = (lane >> 4) * 8;
    const uint32_t ones2[2] = {0x3C003C00u, 0x3C003C00u};

    for (int kt = 0; kt < 16; kt++) {
        if (kt + 1 < 16) { issue_kv(kt + 1, (kt + 1) & 1); CP_COMMIT(); CP_WAIT1(); }
        else CP_WAIT0();
        __syncthreads();

        const uint32_t kvb = sb + AT_OFF_KV + (kt & 1) * AT_BUF;

        float s[8][4];
        #pragma unroll
        for (int j = 0; j < 8; j++)
            #pragma unroll
            for (int q = 0; q < 4; q++) s[j][q] = 0.f;

        #pragma unroll
        for (int k16 = 0; k16 < 4; k16++) {
            uint32_t ah[4];
            const uint32_t qo = q_lrow * AT_STR + (k16 * 16 + q_koff) * 2;
            ldsm_x4(ah, sb + qo);
            #pragma unroll
            for (int jj = 0; jj < 4; jj++) {
                uint32_t kh[4];
                const uint32_t ko = (uint32_t)(16 * jj + k_nrow) * AT_STR
                                  + (k16 * 16 + k_koff) * 2;
                ldsm_x4(kh, kvb + AT_K + ko);
                mma16816h(s[2*jj],   ah, &kh[0]);
                mma16816h(s[2*jj+1], ah, &kh[2]);
            }
        }

        float mx0 = -1e30f, mx1 = -1e30f;
        #pragma unroll
        for (int j = 0; j < 8; j++) {
            mx0 = fmaxf(mx0, fmaxf(s[j][0], s[j][1]));
            mx1 = fmaxf(mx1, fmaxf(s[j][2], s[j][3]));
        }
        mx0 = fmaxf(mx0, __shfl_xor_sync(0xffffffffu, mx0, 1));
        mx0 = fmaxf(mx0, __shfl_xor_sync(0xffffffffu, mx0, 2));
        mx1 = fmaxf(mx1, __shfl_xor_sync(0xffffffffu, mx1, 1));
        mx1 = fmaxf(mx1, __shfl_xor_sync(0xffffffffu, mx1, 2));
        const float mn0 = fmaxf(m0r, mx0);
        const float mn1 = fmaxf(m1r, mx1);
        const float al0 = ex2f(m0r - mn0);
        const float al1 = ex2f(m1r - mn1);
        m0r = mn0; m1r = mn1;

        uint32_t ph[8][2];
        #pragma unroll
        for (int j = 0; j < 8; j++) {
            ph[j][0] = h2exp2(f16x2_of(s[j][0] - mn0, s[j][1] - mn0));
            ph[j][1] = h2exp2(f16x2_of(s[j][2] - mn1, s[j][3] - mn1));
        }

        float lacc[4] = {0.f, 0.f, 0.f, 0.f};
        #pragma unroll
        for (int kk = 0; kk < 4; kk++) {
            uint32_t aph[4] = {ph[2*kk][0], ph[2*kk][1], ph[2*kk+1][0], ph[2*kk+1][1]};
            mma16816h(lacc, aph, ones2);
        }
        l0r = l0r * al0 + lacc[0];
        l1r = l1r * al1 + lacc[2];

        #pragma unroll
        for (int j = 0; j < 8; j++) {
            O[j][0] *= al0; O[j][1] *= al0; O[j][2] *= al1; O[j][3] *= al1;
        }

        #pragma unroll
        for (int kk = 0; kk < 4; kk++) {
            uint32_t aph[4] = {ph[2*kk][0], ph[2*kk][1], ph[2*kk+1][0], ph[2*kk+1][1]};
            #pragma unroll
            for (int jp = 0; jp < 8; jp += 2) {
                uint32_t vh[4];
                const uint32_t vo = (uint32_t)(kk * 16 + v_row_l) * AT_STR
                                  + (8 * jp + v_coladd) * 2;
                ldsm_x4_t(vh, kvb + AT_V + vo);
                mma16816h(O[jp],     aph, &vh[0]);
                mma16816h(O[jp + 1], aph, &vh[2]);
            }
        }
        __syncthreads();
    }

    const float inv0 = 1.f / l0r;
    const float inv1 = 1.f / l1r;
    const int row0 = rowbase + 16 * warp + g;
    const int row1 = row0 + 8;
    #pragma unroll
    for (int j = 0; j < 8; j++) {
        const int col = h * Cc + 8 * j + 2 * t;
        *(uint32_t*)(out + (size_t)row0 * Ww + col) =
            hpack(__float2half(O[j][0] * inv0), __float2half(O[j][1] * inv0));
        *(uint32_t*)(out + (size_t)row1 * Ww + col) =
            hpack(__float2half(O[j][2] * inv1), __float2half(O[j][3] * inv1));
    }
}

// ---------------- launcher ----------------
extern "C" void kernel_launch(void* const* d_in, const int* in_sizes, int n_in,
                              void* d_out, int out_size)
{
    const float* x    = (const float*)d_in[0];
    const float* Wqkv = (const float*)d_in[1];
    const float* bqkv = (const float*)d_in[2];
    const float* Wo   = (const float*)d_in[3];
    const float* bo   = (const float*)d_in[4];
    const float* Wfc  = (const float*)d_in[5];
    const float* bfc  = (const float*)d_in[6];
    const float* Wpr  = (const float*)d_in[7];
    const float* bpr  = (const float*)d_in[8];
    const float* g1   = (const float*)d_in[9];
    const float* b1   = (const float*)d_in[10];
    const float* g2   = (const float*)d_in[11];
    const float* b2   = (const float*)d_in[12];

    float* h = (float*)d_out;

    __half *pqkv, *py, *pat, *pfc, *wq, *wo, *wf, *wp;
    cudaGetSymbolAddress((void**)&pqkv, g_qkv);
    cudaGetSymbolAddress((void**)&py,   g_y);
    cudaGetSymbolAddress((void**)&pat,  g_at);
    cudaGetSymbolAddress((void**)&pfc,  g_fc);
    cudaGetSymbolAddress((void**)&wq,   g_wq);
    cudaGetSymbolAddress((void**)&wo,   g_wo);
    cudaGetSymbolAddress((void**)&wf,   g_wf);
    cudaGetSymbolAddress((void**)&wp,   g_wp);

    cudaFuncSetAttribute(gemm_tc<0,0,2,1>, cudaFuncAttributeMaxDynamicSharedMemorySize, GEMM_SMEM);
    cudaFuncSetAttribute(gemm_tc<0,1,2,0>, cudaFuncAttributeMaxDynamicSharedMemorySize, GEMM_SMEM);
    cudaFuncSetAttribute(gemm_tc<1,0,0,0>, cudaFuncAttributeMaxDynamicSharedMemorySize, GEMM_SMEM);
    cudaFuncSetAttribute(attn_tc,          cudaFuncAttributeMaxDynamicSharedMemorySize, ATTN_SMEM);

    cudaMemcpyAsync(h, x, (size_t)ROWS * Ww * sizeof(float), cudaMemcpyDeviceToDevice);

    {
        int n4;
        n4 = Lnum * Ww * 3 * Ww / 4;
        cvt16_kernel<<<(n4 + 255) / 256, 256>>>((const float4*)Wqkv, (uint2*)wq, n4);
        n4 = Lnum * Ww * Ww / 4;
        cvt16_kernel<<<(n4 + 255) / 256, 256>>>((const float4*)Wo,   (uint2*)wo, n4);
        n4 = Lnum * Ww * 4 * Ww / 4;
        cvt16_kernel<<<(n4 + 255) / 256, 256>>>((const float4*)Wfc,  (uint2*)wf, n4);
        n4 = Lnum * 4 * Ww * Ww / 4;
        cvt16_kernel<<<(n4 + 255) / 256, 256>>>((const float4*)Wpr,  (uint2*)wp, n4);
    }

    for (int l = 0; l < Lnum; l++) {
        const size_t oq = (size_t)l * Ww * 3 * Ww;
        const size_t oo = (size_t)l * Ww * Ww;
        const size_t of = (size_t)l * Ww * 4 * Ww;
        const size_t op = (size_t)l * 4 * Ww * Ww;
        const float* bq  = bqkv + (size_t)l * 3 * Ww;
        const float* bo_ = bo   + (size_t)l * Ww;
        const float* bf  = bfc  + (size_t)l * 4 * Ww;
        const float* bp  = bpr  + (size_t)l * Ww;

        ln_kernel<<<ROWS / 8, 256>>>(h, g1 + l * Ww, b1 + l * Ww, py);
        gemm_tc<0,0,2,1><<<dim3(3 * Ww / 128, ROWS / 128), 256, GEMM_SMEM>>>(
            py, wq + oq, bq, nullptr, nullptr, pqkv, ROWS, Ww, 3 * Ww);
        attn_tc<<<Bb * Hh * (Nn / 128), 256, ATTN_SMEM>>>(pqkv, pat);
        gemm_tc<1,0,0,0><<<dim3(Ww / 128, ROWS / 128), 256, GEMM_SMEM>>>(
            pat, wo + oo, bo_, h, h, nullptr, ROWS, Ww, Ww);
        ln_kernel<<<ROWS / 8, 256>>>(h, g2 + l * Ww, b2 + l * Ww, py);
        gemm_tc<0,1,2,0><<<dim3(4 * Ww / 128, ROWS / 128), 256, GEMM_SMEM>>>(
            py, wf + of, bf, nullptr, nullptr, pfc, ROWS, Ww, 4 * Ww);
        gemm_tc<1,0,0,0><<<dim3(Ww / 128, ROWS / 128), 256, GEMM_SMEM>>>(
            pfc, wp + op, bp, h, h, nullptr, ROWS, 4 * Ww, Ww);
    }
}